// round 2
// baseline (speedup 1.0000x reference)
#include <cuda_runtime.h>

#define NN 50000
#define EE 800000
#define DD 128
#define SLOPE 0.2f

// ---------------- device scratch (static, no allocation) ----------------
__device__ float g_xl[NN * DD];   // lin_l(x) for current layer
__device__ float g_xr[NN * DD];   // lin_r(x) for current layer
__device__ float g_h1[NN * DD];   // layer-1 output
__device__ int   g_rowptr[NN + 1];
__device__ int   g_cnt[NN];
__device__ int   g_cursor[NN];
__device__ int   g_srcs[EE];      // edge sources sorted by dst (CSR payload)
__device__ int   g_is64;          // 1 if edge_index is int64, 0 if int32

// ---------------- packed f32x2 helpers (Blackwell) ----------------
__device__ __forceinline__ unsigned long long pk2(float a, float b) {
    unsigned long long r;
    asm("mov.b64 %0, {%1, %2};" : "=l"(r) : "f"(a), "f"(b));
    return r;
}
__device__ __forceinline__ void upk2(unsigned long long v, float& a, float& b) {
    asm("mov.b64 {%0, %1}, %2;" : "=f"(a), "=f"(b) : "l"(v));
}
__device__ __forceinline__ unsigned long long ff2(unsigned long long a,
                                                  unsigned long long b,
                                                  unsigned long long c) {
    unsigned long long d;
    asm("fma.rn.f32x2 %0, %1, %2, %3;" : "=l"(d) : "l"(a), "l"(b), "l"(c));
    return d;
}

// ---------------- dtype probe ----------------
// int64 edge data: every odd 32-bit word (high word of values < 50000) is 0.
// int32 edge data: odd words are node ids, ~never all zero across 64 samples.
__global__ void k_detect(const int* __restrict__ ei32) {
    if (threadIdx.x == 0 && blockIdx.x == 0) {
        int nz = 0;
        for (int i = 0; i < 64; i++) nz += (ei32[2 * i + 1] != 0);
        g_is64 = (nz == 0) ? 1 : 0;
    }
}

__device__ __forceinline__ int ld_edge(const int* ei32, int elem) {
    // element index in the logical [2*E] int array
    int v = g_is64 ? ei32[2 * elem] : ei32[elem];
    v = v < 0 ? 0 : (v >= NN ? NN - 1 : v);   // clamp: never trap
    return v;
}

// ---------------- CSR build ----------------
__global__ void k_zero() {
    int i = blockIdx.x * blockDim.x + threadIdx.x;
    if (i < NN) g_cnt[i] = 0;
}

__global__ void k_hist(const int* __restrict__ ei32) {
    int e = blockIdx.x * blockDim.x + threadIdx.x;
    if (e < EE) {
        int d = ld_edge(ei32, EE + e);
        atomicAdd(&g_cnt[d], 1);
    }
}

// Single-block exclusive scan over g_cnt -> g_rowptr / g_cursor
__global__ void k_scan() {
    __shared__ int wsums[32];
    __shared__ int s_total;
    int tid = threadIdx.x, lane = tid & 31, wid = tid >> 5;
    int carry = 0;
    for (int base = 0; base < NN; base += 1024) {
        int i = base + tid;
        int v = (i < NN) ? g_cnt[i] : 0;
        int x = v;
#pragma unroll
        for (int off = 1; off < 32; off <<= 1) {
            int t = __shfl_up_sync(0xffffffffu, x, off);
            if (lane >= off) x += t;
        }
        if (lane == 31) wsums[wid] = x;
        __syncthreads();
        if (wid == 0) {
            int y = wsums[lane];
            int z = y;
#pragma unroll
            for (int off = 1; off < 32; off <<= 1) {
                int t = __shfl_up_sync(0xffffffffu, z, off);
                if (lane >= off) z += t;
            }
            wsums[lane] = z - y;          // exclusive warp offsets
            if (lane == 31) s_total = z;  // block total
        }
        __syncthreads();
        int excl = carry + wsums[wid] + (x - v);
        if (i < NN) { g_rowptr[i] = excl; g_cursor[i] = excl; }
        carry += s_total;
        __syncthreads();
    }
    if (tid == 0) g_rowptr[NN] = carry;
}

__global__ void k_scatter(const int* __restrict__ ei32) {
    int e = blockIdx.x * blockDim.x + threadIdx.x;
    if (e < EE) {
        int d = ld_edge(ei32, EE + e);
        int s = ld_edge(ei32, e);
        int pos = atomicAdd(&g_cursor[d], 1);
        g_srcs[pos] = s;
    }
}

// ---------------- GEMM: writes g_xl (from W0,b0) and g_xr (from W1,b1) ----------------
// Tile: 64 rows x 128 cols, 256 threads, thread-tile 8x4 via f32x2 packed accs.
// blockIdx.y selects (W0,b0)->g_xl vs (W1,b1)->g_xr so the x tile is shared.
__global__ __launch_bounds__(256) void k_gemm(
    const float* __restrict__ x, int x_from_h1,
    const float* __restrict__ W0, const float* __restrict__ b0,
    const float* __restrict__ W1, const float* __restrict__ b1)
{
    __shared__ float xs[32][68];   // x tile transposed [k][row], padded
    __shared__ float ws[32 * 128]; // W chunk rows k0..k0+31 (row-major)

    const float* xx = x_from_h1 ? g_h1 : x;
    const float* W  = blockIdx.y ? W1 : W0;
    const float* bb = blockIdx.y ? b1 : b0;
    float* out      = blockIdx.y ? g_xr : g_xl;

    const int row0 = blockIdx.x * 64;
    const int tid = threadIdx.x;
    const int tx = tid & 31;   // col group (4 cols)
    const int ty = tid >> 5;   // row group (8 rows)

    unsigned long long acc[8][2];
#pragma unroll
    for (int i = 0; i < 8; i++) { acc[i][0] = 0ull; acc[i][1] = 0ull; }

    for (int k0 = 0; k0 < 128; k0 += 32) {
#pragma unroll
        for (int t = 0; t < 2; t++) {
            int idx = tid * 2 + t;          // 0..511
            int r = idx >> 3;               // local row 0..63
            int kq = idx & 7;               // float4 index along k
            int gr = row0 + r;
            float4 v = make_float4(0.f, 0.f, 0.f, 0.f);
            if (gr < NN) v = *(const float4*)&xx[gr * 128 + k0 + kq * 4];
            xs[kq * 4 + 0][r] = v.x;
            xs[kq * 4 + 1][r] = v.y;
            xs[kq * 4 + 2][r] = v.z;
            xs[kq * 4 + 3][r] = v.w;
        }
#pragma unroll
        for (int q = 0; q < 4; q++) {
            int off = (tid + q * 256) * 4;
            *(float4*)&ws[off] = *(const float4*)&W[k0 * 128 + off];
        }
        __syncthreads();

#pragma unroll
        for (int k = 0; k < 32; k++) {
            float4 a0 = *(const float4*)&xs[k][ty * 8];
            float4 a1 = *(const float4*)&xs[k][ty * 8 + 4];
            ulonglong2 wv = *(const ulonglong2*)&ws[k * 128 + tx * 4];
            unsigned long long p;
            p = pk2(a0.x, a0.x); acc[0][0] = ff2(p, wv.x, acc[0][0]); acc[0][1] = ff2(p, wv.y, acc[0][1]);
            p = pk2(a0.y, a0.y); acc[1][0] = ff2(p, wv.x, acc[1][0]); acc[1][1] = ff2(p, wv.y, acc[1][1]);
            p = pk2(a0.z, a0.z); acc[2][0] = ff2(p, wv.x, acc[2][0]); acc[2][1] = ff2(p, wv.y, acc[2][1]);
            p = pk2(a0.w, a0.w); acc[3][0] = ff2(p, wv.x, acc[3][0]); acc[3][1] = ff2(p, wv.y, acc[3][1]);
            p = pk2(a1.x, a1.x); acc[4][0] = ff2(p, wv.x, acc[4][0]); acc[4][1] = ff2(p, wv.y, acc[4][1]);
            p = pk2(a1.y, a1.y); acc[5][0] = ff2(p, wv.x, acc[5][0]); acc[5][1] = ff2(p, wv.y, acc[5][1]);
            p = pk2(a1.z, a1.z); acc[6][0] = ff2(p, wv.x, acc[6][0]); acc[6][1] = ff2(p, wv.y, acc[6][1]);
            p = pk2(a1.w, a1.w); acc[7][0] = ff2(p, wv.x, acc[7][0]); acc[7][1] = ff2(p, wv.y, acc[7][1]);
        }
        __syncthreads();
    }

    float4 b4 = *(const float4*)&bb[tx * 4];
#pragma unroll
    for (int i = 0; i < 8; i++) {
        int r = row0 + ty * 8 + i;
        if (r < NN) {
            float4 o;
            upk2(acc[i][0], o.x, o.y);
            upk2(acc[i][1], o.z, o.w);
            o.x += b4.x; o.y += b4.y; o.z += b4.z; o.w += b4.w;
            *(float4*)&out[r * 128 + tx * 4] = o;
        }
    }
}

// ---------------- fused attention + aggregation ----------------
// One warp per dst node v. For each incoming edge (CSR, srcs sorted by dst):
//   z = leaky_relu(xl[src] + xr[v]); logit = z.att (warp butterfly)
//   w = exp(logit); acc += w * xl[src]; wsum += w
// out[v] = relu(acc / max(wsum,1e-16) + bias)
// (softmax max-shift cancels in the ratio; logits are O(10), exp never overflows)
__global__ __launch_bounds__(256) void k_aggregate(
    const float* __restrict__ att, const float* __restrict__ bias,
    float* __restrict__ out, int out_to_h1)
{
    int gw = (blockIdx.x * blockDim.x + threadIdx.x) >> 5;
    int lane = threadIdx.x & 31;
    if (gw >= NN) return;

    float* o = out_to_h1 ? g_h1 : out;

    int beg = g_rowptr[gw];
    int end = g_rowptr[gw + 1];

    float4 xrv = *(const float4*)&g_xr[(size_t)gw * 128 + lane * 4];
    float4 at4 = *(const float4*)&att[lane * 4];

    float4 acc = make_float4(0.f, 0.f, 0.f, 0.f);
    float wsum = 0.f;

    int sA = (beg < end) ? g_srcs[beg] : 0;   // src prefetch
    for (int j = beg; j < end; j++) {
        int s = sA;
        if (j + 1 < end) sA = g_srcs[j + 1];
        float4 xv = *(const float4*)&g_xl[(size_t)s * 128 + lane * 4];

        float z0 = xv.x + xrv.x; z0 = z0 > 0.f ? z0 : SLOPE * z0;
        float z1 = xv.y + xrv.y; z1 = z1 > 0.f ? z1 : SLOPE * z1;
        float z2 = xv.z + xrv.z; z2 = z2 > 0.f ? z2 : SLOPE * z2;
        float z3 = xv.w + xrv.w; z3 = z3 > 0.f ? z3 : SLOPE * z3;
        float part = z0 * at4.x + z1 * at4.y + z2 * at4.z + z3 * at4.w;

        part += __shfl_xor_sync(0xffffffffu, part, 16);
        part += __shfl_xor_sync(0xffffffffu, part, 8);
        part += __shfl_xor_sync(0xffffffffu, part, 4);
        part += __shfl_xor_sync(0xffffffffu, part, 2);
        part += __shfl_xor_sync(0xffffffffu, part, 1);

        float w = __expf(part);
        acc.x += w * xv.x;
        acc.y += w * xv.y;
        acc.z += w * xv.z;
        acc.w += w * xv.w;
        wsum += w;
    }

    float inv = 1.f / fmaxf(wsum, 1e-16f);
    float4 b4 = *(const float4*)&bias[lane * 4];
    float4 r;
    r.x = fmaxf(acc.x * inv + b4.x, 0.f);
    r.y = fmaxf(acc.y * inv + b4.y, 0.f);
    r.z = fmaxf(acc.z * inv + b4.z, 0.f);
    r.w = fmaxf(acc.w * inv + b4.w, 0.f);
    *(float4*)&o[(size_t)gw * 128 + lane * 4] = r;
}

// ---------------- launch ----------------
extern "C" void kernel_launch(void* const* d_in, const int* in_sizes, int n_in,
                              void* d_out, int out_size) {
    const float* x0    = (const float*)d_in[0];
    const int*   ei32  = (const int*)d_in[1];   // int32 or int64 (auto-detected)
    const float* Wl1   = (const float*)d_in[2];
    const float* bl1   = (const float*)d_in[3];
    const float* Wr1   = (const float*)d_in[4];
    const float* br1   = (const float*)d_in[5];
    const float* att1  = (const float*)d_in[6];
    const float* bias1 = (const float*)d_in[7];
    const float* Wl2   = (const float*)d_in[8];
    const float* bl2   = (const float*)d_in[9];
    const float* Wr2   = (const float*)d_in[10];
    const float* br2   = (const float*)d_in[11];
    const float* att2  = (const float*)d_in[12];
    const float* bias2 = (const float*)d_in[13];
    float* out = (float*)d_out;

    // CSR build (graph identical for both layers)
    k_detect<<<1, 32>>>(ei32);
    k_zero<<<(NN + 255) / 256, 256>>>();
    k_hist<<<(EE + 255) / 256, 256>>>(ei32);
    k_scan<<<1, 1024>>>();
    k_scatter<<<(EE + 255) / 256, 256>>>(ei32);

    dim3 ggrid((NN + 63) / 64, 2);

    // layer 1
    k_gemm<<<ggrid, 256>>>(x0, 0, Wl1, bl1, Wr1, br1);
    k_aggregate<<<(NN * 32 + 255) / 256, 256>>>(att1, bias1, out, 1);

    // layer 2
    k_gemm<<<ggrid, 256>>>(x0, 1, Wl2, bl2, Wr2, br2);
    k_aggregate<<<(NN * 32 + 255) / 256, 256>>>(att2, bias2, out, 0);
}